// round 13
// baseline (speedup 1.0000x reference)
#include <cuda_runtime.h>
#include <cstdint>

// ---------------- problem dims (fixed) ----------------
#define BDIM 8192
#define KDIM 4096
#define N2   1024
#define KW   (KDIM / 32)   // 128 k-words

// ---------------- device scratch (no mallocs allowed) ----------------
__device__ uint32_t g_Ap[(size_t)KW * BDIM];   // packed activations [w][row]
__device__ uint32_t g_Bp[(size_t)KW * KDIM];   // packed weights [w][n]
__device__ short    g_S16[(size_t)BDIM * KDIM];
__device__ int                g_colsum[3][KDIM];   // per-layer colsum
__device__ unsigned long long g_sumsq[N2];
__device__ int                g_cmax[N2];
__device__ float              g_expsum[N2];

// ---------------- helpers ----------------
__device__ __forceinline__ uint32_t smem_u32(const void* p) {
    uint32_t a;
    asm("{ .reg .u64 t; cvta.to.shared.u64 t, %1; cvt.u32.u64 %0, t; }" : "=r"(a) : "l"(p));
    return a;
}
__device__ __forceinline__ void cp16(uint32_t s, const void* g) {
    asm volatile("cp.async.cg.shared.global [%0], [%1], 16;" :: "r"(s), "l"(g));
}
#define CP_COMMIT() asm volatile("cp.async.commit_group;" ::: "memory")
#define CP_WAITN(n) asm volatile("cp.async.wait_group %0;" :: "n"(n) : "memory")

__device__ __forceinline__ void ld4(uint32_t* d, const uint32_t* p) {
    uint4 t = *(const uint4*)p; d[0] = t.x; d[1] = t.y; d[2] = t.z; d[3] = t.w;
}
// full adder on bit-planes: s = a^b^c (LOP3 0x96), carry = maj(a,b,c) (LOP3 0xE8)
__device__ __forceinline__ void fa(uint32_t a, uint32_t b, uint32_t c,
                                   uint32_t& s, uint32_t& cy) {
    asm("lop3.b32 %0, %2, %3, %4, 0x96;\n\t"
        "lop3.b32 %1, %2, %3, %4, 0xE8;"
        : "=r"(s), "=r"(cy) : "r"(a), "r"(b), "r"(c));
}

// ---------------- XNOR-popc GEMM with CSA compression (frozen from R12) ----------
// CTA tile 64x64, 256 thr, thread tile 4x4. Two 64-kw stages (32KB each,
// dynamic smem 64KB, 2 CTAs/SM) -> only 2 barriers per tile.
#define STG_W 8192     // words per stage (A 4096 + B 4096)
#define GEMM_SMEM (STG_W * 4 * 2)

__global__ void __launch_bounds__(256, 2) k_gemm(int N, int layer, int doStats,
                                                 int one, int two, int four) {
    extern __shared__ __align__(16) uint32_t smem[];
    const uint32_t sb = smem_u32(smem);
    const int tid = threadIdx.x;
    // bijective remap: tx = {b2b1b0, b7}, ty = {b6..b3}
    const int tx = (tid & 7) | ((tid >> 4) & 8);
    const int ty = (tid >> 3) & 15;
    const size_t m0 = (size_t)blockIdx.y * 64;
    const size_t n0 = (size_t)blockIdx.x * 64;

    const uint32_t* Ab = g_Ap + m0;   // + w*BDIM + m
    const uint32_t* Bb = g_Bp + n0;   // + w*N + n

    auto load_chunk = [&](int c, int st) {
        uint32_t base = sb + st * (STG_W * 4);
#pragma unroll
        for (int i = 0; i < 4; i++) {
            int idx = tid + i * 256;                 // 0..1023 : 64 kw x 16 segs
            int kw = idx >> 4, seg = idx & 15;
            cp16(base + kw * 256 + seg * 16,
                 Ab + (size_t)(c * 64 + kw) * BDIM + seg * 4);
            cp16(base + 16384 + kw * 256 + seg * 16,
                 Bb + (size_t)(c * 64 + kw) * N + seg * 4);
        }
    };

    int acc[4][4];
#pragma unroll
    for (int i = 0; i < 4; i++)
#pragma unroll
        for (int j = 0; j < 4; j++) acc[i][j] = 0;

    load_chunk(0, 0); CP_COMMIT();
    load_chunk(1, 1); CP_COMMIT();

    auto compute_chunk = [&](const uint32_t* stp) {
#pragma unroll
        for (int g = 0; g < 8; g++) {
            const uint32_t* gp = stp + g * 512;      // 8-kw group
            uint32_t a[8][4], b[8][4];
#pragma unroll
            for (int w = 0; w < 8; w++) {
                ld4(a[w], gp + w * 64 + ty * 4);
                ld4(b[w], gp + 4096 + w * 64 + tx * 4);
            }
#pragma unroll
            for (int i = 0; i < 4; i++)
#pragma unroll
                for (int j = 0; j < 4; j++) {
                    uint32_t x0 = a[0][i] ^ b[0][j], x1 = a[1][i] ^ b[1][j];
                    uint32_t x2 = a[2][i] ^ b[2][j], x3 = a[3][i] ^ b[3][j];
                    uint32_t x4 = a[4][i] ^ b[4][j], x5 = a[5][i] ^ b[5][j];
                    uint32_t x6 = a[6][i] ^ b[6][j], x7 = a[7][i] ^ b[7][j];
                    uint32_t s1, c1, s2, c2, s3, c3, s5, c5;
                    fa(x0, x1, x2, s1, c1);     // -> s1(w1), c1(w2)
                    fa(x3, x4, x5, s2, c2);     // -> s2(w1), c2(w2)
                    fa(s1, s2, x6, s3, c3);     // -> s3(w1), c3(w2)
                    fa(c1, c2, c3, s5, c5);     // -> s5(w2), c5(w4)
                    // remaining planes: s3(w1), x7(w1), s5(w2), c5(w4)
                    int p0 = __popc(s3), p1 = __popc(x7);
                    int p2 = __popc(s5), p3 = __popc(c5);
                    // weighted accumulate on fma pipe; weights are kernel args
                    // so ptxas cannot strength-reduce mad -> add
                    asm("mad.lo.s32 %0, %1, %5, %0;\n\t"
                        "mad.lo.s32 %0, %2, %5, %0;\n\t"
                        "mad.lo.s32 %0, %3, %6, %0;\n\t"
                        "mad.lo.s32 %0, %4, %7, %0;"
                        : "+r"(acc[i][j])
                        : "r"(p0), "r"(p1), "r"(p2), "r"(p3),
                          "r"(one), "r"(two), "r"(four));
                }
        }
    };

    CP_WAITN(1);
    __syncthreads();
    compute_chunk(smem);
    CP_WAITN(0);
    __syncthreads();
    compute_chunk(smem + STG_W);
    __syncthreads();   // k-loop smem dead; reuse for reductions below

    // ---- epilogue 1: s = 4096 - 2*P, exact int16 stores ----
#pragma unroll
    for (int i = 0; i < 4; i++) {
        size_t row = m0 + ty * 4 + i;
        int s0 = 4096 - 2 * acc[i][0], s1 = 4096 - 2 * acc[i][1];
        int s2 = 4096 - 2 * acc[i][2], s3 = 4096 - 2 * acc[i][3];
        uint32_t lo = (uint16_t)s0 | ((uint32_t)(uint16_t)s1 << 16);
        uint32_t hi = (uint16_t)s2 | ((uint32_t)(uint16_t)s3 << 16);
        *(uint2*)&g_S16[row * N + n0 + tx * 4] = make_uint2(lo, hi);
    }

    // ---- epilogue 2: fused per-column reductions ----
    int* colbuf = (int*)smem;
    unsigned* sqbuf = (unsigned*)smem + 64;
    int* mxbuf = (int*)smem + 128;
    if (tid < 64) {
        colbuf[tid] = 0;
        if (doStats) { sqbuf[tid] = 0u; mxbuf[tid] = -2147483647 - 1; }
    }
    __syncthreads();
#pragma unroll
    for (int j = 0; j < 4; j++) {
        int cl = tx * 4 + j;
        int cs = 4 * 4096 - 2 * (acc[0][j] + acc[1][j] + acc[2][j] + acc[3][j]);
        atomicAdd(&colbuf[cl], cs);
        if (doStats) {
            int sq = 0, mx = -2147483647 - 1;
#pragma unroll
            for (int i = 0; i < 4; i++) {
                int s = 4096 - 2 * acc[i][j];
                sq += s * s; mx = max(mx, s);
            }
            atomicAdd(&sqbuf[cl], (unsigned)sq);
            atomicMax(&mxbuf[cl], mx);
        }
    }
    __syncthreads();
    if (tid < 64) {
        atomicAdd(&g_colsum[layer][n0 + tid], colbuf[tid]);
        if (doStats) {
            atomicAdd(&g_sumsq[n0 + tid], (unsigned long long)sqbuf[tid]);
            atomicMax(&g_cmax[n0 + tid], mxbuf[tid]);
        }
    }
}

// ---------------- fused aux kernels ----------------

// k_pre: blocks [0,4096) binarize x; blocks [4096,4112) zero accumulators.
__global__ void k_pre(const float* __restrict__ x) {
    int b = blockIdx.x, tid = threadIdx.x;
    if (b < 4096) {
        int t = b * 256 + tid;
        int row = t & (BDIM - 1), w = t >> 13;
        const float4* p = (const float4*)(x + (size_t)row * KDIM + w * 32);
        uint32_t word = 0;
#pragma unroll
        for (int q = 0; q < 8; q++) {
            float4 v = p[q];
            word |= (v.x >= 0.5f ? 1u : 0u) << (q * 4 + 0);
            word |= (v.y >= 0.5f ? 1u : 0u) << (q * 4 + 1);
            word |= (v.z >= 0.5f ? 1u : 0u) << (q * 4 + 2);
            word |= (v.w >= 0.5f ? 1u : 0u) << (q * 4 + 3);
        }
        g_Ap[(size_t)w * BDIM + row] = word;
    } else {
        int i = (b - 4096) * 256 + tid;
        if (i < KDIM) { g_colsum[0][i] = 0; g_colsum[1][i] = 0; g_colsum[2][i] = 0; }
        if (i < N2) { g_sumsq[i] = 0ull; g_expsum[i] = 0.f; g_cmax[i] = -2147483647 - 1; }
    }
}

// k_bw: blocks [0,nW) transpose+pack next-layer W; rest binarize activations
// of the just-finished layer (N fixed 4096 for layers 0/1).
__global__ void k_bw(const float* __restrict__ W, int Nw, int nW,
                     const float* __restrict__ gamma, int layer) {
    int b = blockIdx.x, tid = threadIdx.x;
    if (b < nW) {
        // ---- wtrans part: W[K,Nw] f32 -> g_Bp[w][n] packed bits ----
        __shared__ float tbuf[32][33];
        __shared__ uint32_t wbuf[32];
        int gx = Nw / 32;
        int n0 = (b % gx) * 32, k0 = (b / gx) * 32;
        int tx = tid & 31, ty = tid >> 5;   // 32 x 8
#pragma unroll
        for (int q = 0; q < 4; q++)
            tbuf[ty + q * 8][tx] = W[(size_t)(k0 + ty + q * 8) * Nw + n0 + tx];
        __syncthreads();
#pragma unroll
        for (int q = 0; q < 4; q++) {
            int n = ty * 4 + q;
            uint32_t bb = __ballot_sync(0xffffffffu, tbuf[tx][n] >= 0.f);
            if (tx == 0) wbuf[n] = bb;
        }
        __syncthreads();
        if (ty == 0)
            g_Bp[(size_t)(b / gx) * Nw + n0 + tx] = wbuf[tx];
    } else {
        // ---- binact part: bit = (8192*s >= colsum) exactly (gamma>0, beta=0) ----
        const int N = KDIM;   // layers 0/1 have N=4096
        int t = (b - nW) * 256 + tid;
        int row = t & (BDIM - 1), w = t >> 13;
        float g = gamma[layer];
        const uint4* sp = (const uint4*)(g_S16 + (size_t)row * N + w * 32);
        const int4* cp = (const int4*)(&g_colsum[layer][w * 32]);
        uint32_t word = 0;
#pragma unroll
        for (int q = 0; q < 4; q++) {
            uint4 u = sp[q];
            int4 c0 = cp[2 * q], c1 = cp[2 * q + 1];
            int s0 = (short)(u.x & 0xFFFF), s1 = (short)(u.x >> 16);
            int s2 = (short)(u.y & 0xFFFF), s3 = (short)(u.y >> 16);
            int s4 = (short)(u.z & 0xFFFF), s5 = (short)(u.z >> 16);
            int s6 = (short)(u.w & 0xFFFF), s7 = (short)(u.w >> 16);
            word |= (s0 * 8192 >= c0.x ? 1u : 0u) << (q * 8 + 0);
            word |= (s1 * 8192 >= c0.y ? 1u : 0u) << (q * 8 + 1);
            word |= (s2 * 8192 >= c0.z ? 1u : 0u) << (q * 8 + 2);
            word |= (s3 * 8192 >= c0.w ? 1u : 0u) << (q * 8 + 3);
            word |= (s4 * 8192 >= c1.x ? 1u : 0u) << (q * 8 + 4);
            word |= (s5 * 8192 >= c1.y ? 1u : 0u) << (q * 8 + 5);
            word |= (s6 * 8192 >= c1.z ? 1u : 0u) << (q * 8 + 6);
            word |= (s7 * 8192 >= c1.w ? 1u : 0u) << (q * 8 + 7);
        }
        if (g <= 0.f) word = 0xFFFFFFFFu;   // a == beta == 0 -> +1
        g_Ap[(size_t)w * BDIM + row] = word;
    }
}

// per-column BN params derived identically in both softmax passes
__device__ __forceinline__ void bn_params(int col, const float* gamma,
                                          float& g, float& mu, float& am) {
    double sum = (double)g_colsum[2][col];
    double dmu = sum * (1.0 / 8192.0);
    double var = (double)g_sumsq[col] * (1.0 / 8192.0) - dmu * dmu;
    g = (float)((double)gamma[2] / sqrt(var + 1e-5));
    mu = (float)dmu;
    am = ((float)g_cmax[col] - mu) * g;   // beta cancels in softmax
}

// pass 1: expsum only (no exp store)
__global__ void k_soft1(const float* __restrict__ gamma) {
    const int N = N2;
    int col = blockIdx.x * 256 + threadIdx.x;
    size_t r0 = (size_t)blockIdx.y * 64;
    float g, mu, am;
    bn_params(col, gamma, g, mu, am);
    const short* p = g_S16 + r0 * N + col;
    float acc = 0.f;
    for (int r = 0; r < 64; r++)
        acc += expf(((float)p[(size_t)r * N] - mu) * g - am);
    atomicAdd(&g_expsum[col], acc);
}

// pass 2: recompute exp (bit-identical expf), normalize, write out
__global__ void k_soft2(float* __restrict__ out, const float* __restrict__ gamma) {
    const int N = N2;
    int col = blockIdx.x * 256 + threadIdx.x;
    size_t r0 = (size_t)blockIdx.y * 64;
    float g, mu, am;
    bn_params(col, gamma, g, mu, am);
    float inv = 1.0f / g_expsum[col];
    const short* p = g_S16 + r0 * N + col;
    float* o = out + r0 * N + col;
    for (int r = 0; r < 64; r++) {
        float e = expf(((float)p[(size_t)r * N] - mu) * g - am);
        o[(size_t)r * N] = e * inv;
    }
}

// ---------------- launch ----------------
extern "C" void kernel_launch(void* const* d_in, const int* in_sizes, int n_in,
                              void* d_out, int out_size) {
    const float* x     = (const float*)d_in[0];
    const float* W0    = (const float*)d_in[1];
    const float* W1    = (const float*)d_in[2];
    const float* W2    = (const float*)d_in[3];
    const float* gamma = (const float*)d_in[4];
    float* out = (float*)d_out;

    cudaFuncSetAttribute(k_gemm, cudaFuncAttributeMaxDynamicSharedMemorySize, GEMM_SMEM);

    // wtrans0 runs standalone (nW = full grid, no binact part)
    k_pre<<<4112, 256>>>(x);
    k_bw<<<16384, 256>>>(W0, 4096, 16384, gamma, 0);
    k_gemm<<<dim3(64, 128), 256, GEMM_SMEM>>>(4096, 0, 0, 1, 2, 4);
    k_bw<<<20480, 256>>>(W1, 4096, 16384, gamma, 0);   // wtrans W1 + binact L0
    k_gemm<<<dim3(64, 128), 256, GEMM_SMEM>>>(4096, 1, 0, 1, 2, 4);
    k_bw<<<8192, 256>>>(W2, 1024, 4096, gamma, 1);     // wtrans W2 + binact L1
    k_gemm<<<dim3(16, 128), 256, GEMM_SMEM>>>(1024, 2, 1, 1, 2, 4);
    k_soft1<<<dim3(4, 128), 256>>>(gamma);
    k_soft2<<<dim3(4, 128), 256>>>(out, gamma);
}

// round 14
// speedup vs baseline: 1.0033x; 1.0033x over previous
#include <cuda_runtime.h>
#include <cstdint>

// ---------------- problem dims (fixed) ----------------
#define BDIM 8192
#define KDIM 4096
#define N2   1024
#define KW   (KDIM / 32)   // 128 k-words

// ---------------- device scratch (no mallocs allowed) ----------------
__device__ uint32_t g_Ap[(size_t)KW * BDIM];   // packed activations [w][row]
__device__ uint32_t g_Bp[(size_t)KW * KDIM];   // packed weights [w][n]
__device__ short    g_S16[(size_t)BDIM * KDIM];
__device__ int                g_colsum[3][KDIM];   // per-layer colsum
__device__ unsigned long long g_sumsq[N2];
__device__ int                g_cmax[N2];
__device__ float              g_expsum[N2];

// ---------------- helpers ----------------
__device__ __forceinline__ uint32_t smem_u32(const void* p) {
    uint32_t a;
    asm("{ .reg .u64 t; cvta.to.shared.u64 t, %1; cvt.u32.u64 %0, t; }" : "=r"(a) : "l"(p));
    return a;
}
__device__ __forceinline__ void cp16(uint32_t s, const void* g) {
    asm volatile("cp.async.cg.shared.global [%0], [%1], 16;" :: "r"(s), "l"(g));
}
#define CP_COMMIT() asm volatile("cp.async.commit_group;" ::: "memory")
#define CP_WAITN(n) asm volatile("cp.async.wait_group %0;" :: "n"(n) : "memory")

__device__ __forceinline__ void ld4(uint32_t* d, const uint32_t* p) {
    uint4 t = *(const uint4*)p; d[0] = t.x; d[1] = t.y; d[2] = t.z; d[3] = t.w;
}
// full adder on bit-planes: s = a^b^c (LOP3 0x96), carry = maj(a,b,c) (LOP3 0xE8)
__device__ __forceinline__ void fa(uint32_t a, uint32_t b, uint32_t c,
                                   uint32_t& s, uint32_t& cy) {
    asm("lop3.b32 %0, %2, %3, %4, 0x96;\n\t"
        "lop3.b32 %1, %2, %3, %4, 0xE8;"
        : "=r"(s), "=r"(cy) : "r"(a), "r"(b), "r"(c));
}

// ---------------- XNOR-popc GEMM with CSA compression (frozen from R12) ----------
// CTA tile 64x64, 256 thr, thread tile 4x4. Two 64-kw stages (32KB each,
// dynamic smem 64KB, 2 CTAs/SM) -> only 2 barriers per tile.
#define STG_W 8192     // words per stage (A 4096 + B 4096)
#define GEMM_SMEM (STG_W * 4 * 2)

__global__ void __launch_bounds__(256, 2) k_gemm(int N, int layer, int doStats,
                                                 int one, int two, int four) {
    extern __shared__ __align__(16) uint32_t smem[];
    const uint32_t sb = smem_u32(smem);
    const int tid = threadIdx.x;
    // bijective remap: tx = {b2b1b0, b7}, ty = {b6..b3}
    const int tx = (tid & 7) | ((tid >> 4) & 8);
    const int ty = (tid >> 3) & 15;
    const size_t m0 = (size_t)blockIdx.y * 64;
    const size_t n0 = (size_t)blockIdx.x * 64;

    const uint32_t* Ab = g_Ap + m0;   // + w*BDIM + m
    const uint32_t* Bb = g_Bp + n0;   // + w*N + n

    auto load_chunk = [&](int c, int st) {
        uint32_t base = sb + st * (STG_W * 4);
#pragma unroll
        for (int i = 0; i < 4; i++) {
            int idx = tid + i * 256;                 // 0..1023 : 64 kw x 16 segs
            int kw = idx >> 4, seg = idx & 15;
            cp16(base + kw * 256 + seg * 16,
                 Ab + (size_t)(c * 64 + kw) * BDIM + seg * 4);
            cp16(base + 16384 + kw * 256 + seg * 16,
                 Bb + (size_t)(c * 64 + kw) * N + seg * 4);
        }
    };

    int acc[4][4];
#pragma unroll
    for (int i = 0; i < 4; i++)
#pragma unroll
        for (int j = 0; j < 4; j++) acc[i][j] = 0;

    load_chunk(0, 0); CP_COMMIT();
    load_chunk(1, 1); CP_COMMIT();

    auto compute_chunk = [&](const uint32_t* stp) {
#pragma unroll
        for (int g = 0; g < 8; g++) {
            const uint32_t* gp = stp + g * 512;      // 8-kw group
            uint32_t a[8][4], b[8][4];
#pragma unroll
            for (int w = 0; w < 8; w++) {
                ld4(a[w], gp + w * 64 + ty * 4);
                ld4(b[w], gp + 4096 + w * 64 + tx * 4);
            }
#pragma unroll
            for (int i = 0; i < 4; i++)
#pragma unroll
                for (int j = 0; j < 4; j++) {
                    uint32_t x0 = a[0][i] ^ b[0][j], x1 = a[1][i] ^ b[1][j];
                    uint32_t x2 = a[2][i] ^ b[2][j], x3 = a[3][i] ^ b[3][j];
                    uint32_t x4 = a[4][i] ^ b[4][j], x5 = a[5][i] ^ b[5][j];
                    uint32_t x6 = a[6][i] ^ b[6][j], x7 = a[7][i] ^ b[7][j];
                    uint32_t s1, c1, s2, c2, s3, c3, s5, c5;
                    fa(x0, x1, x2, s1, c1);     // -> s1(w1), c1(w2)
                    fa(x3, x4, x5, s2, c2);     // -> s2(w1), c2(w2)
                    fa(s1, s2, x6, s3, c3);     // -> s3(w1), c3(w2)
                    fa(c1, c2, c3, s5, c5);     // -> s5(w2), c5(w4)
                    // remaining planes: s3(w1), x7(w1), s5(w2), c5(w4)
                    int p0 = __popc(s3), p1 = __popc(x7);
                    int p2 = __popc(s5), p3 = __popc(c5);
                    // weighted accumulate on fma pipe; weights are kernel args
                    // so ptxas cannot strength-reduce mad -> add
                    asm("mad.lo.s32 %0, %1, %5, %0;\n\t"
                        "mad.lo.s32 %0, %2, %5, %0;\n\t"
                        "mad.lo.s32 %0, %3, %6, %0;\n\t"
                        "mad.lo.s32 %0, %4, %7, %0;"
                        : "+r"(acc[i][j])
                        : "r"(p0), "r"(p1), "r"(p2), "r"(p3),
                          "r"(one), "r"(two), "r"(four));
                }
        }
    };

    CP_WAITN(1);
    __syncthreads();
    compute_chunk(smem);
    CP_WAITN(0);
    __syncthreads();
    compute_chunk(smem + STG_W);
    __syncthreads();   // k-loop smem dead; reuse for reductions below

    // ---- epilogue 1: s = 4096 - 2*P, exact int16 stores ----
#pragma unroll
    for (int i = 0; i < 4; i++) {
        size_t row = m0 + ty * 4 + i;
        int s0 = 4096 - 2 * acc[i][0], s1 = 4096 - 2 * acc[i][1];
        int s2 = 4096 - 2 * acc[i][2], s3 = 4096 - 2 * acc[i][3];
        uint32_t lo = (uint16_t)s0 | ((uint32_t)(uint16_t)s1 << 16);
        uint32_t hi = (uint16_t)s2 | ((uint32_t)(uint16_t)s3 << 16);
        *(uint2*)&g_S16[row * N + n0 + tx * 4] = make_uint2(lo, hi);
    }

    // ---- epilogue 2: fused per-column reductions ----
    int* colbuf = (int*)smem;
    unsigned* sqbuf = (unsigned*)smem + 64;
    int* mxbuf = (int*)smem + 128;
    if (tid < 64) {
        colbuf[tid] = 0;
        if (doStats) { sqbuf[tid] = 0u; mxbuf[tid] = -2147483647 - 1; }
    }
    __syncthreads();
#pragma unroll
    for (int j = 0; j < 4; j++) {
        int cl = tx * 4 + j;
        int cs = 4 * 4096 - 2 * (acc[0][j] + acc[1][j] + acc[2][j] + acc[3][j]);
        atomicAdd(&colbuf[cl], cs);
        if (doStats) {
            int sq = 0, mx = -2147483647 - 1;
#pragma unroll
            for (int i = 0; i < 4; i++) {
                int s = 4096 - 2 * acc[i][j];
                sq += s * s; mx = max(mx, s);
            }
            atomicAdd(&sqbuf[cl], (unsigned)sq);
            atomicMax(&mxbuf[cl], mx);
        }
    }
    __syncthreads();
    if (tid < 64) {
        atomicAdd(&g_colsum[layer][n0 + tid], colbuf[tid]);
        if (doStats) {
            atomicAdd(&g_sumsq[n0 + tid], (unsigned long long)sqbuf[tid]);
            atomicMax(&g_cmax[n0 + tid], mxbuf[tid]);
        }
    }
}

// ---------------- aux kernels ----------------

// k_pre: blocks [0,4096) binarize x; blocks [4096,4112) zero accumulators.
__global__ void k_pre(const float* __restrict__ x) {
    int b = blockIdx.x, tid = threadIdx.x;
    if (b < 4096) {
        int t = b * 256 + tid;
        int row = t & (BDIM - 1), w = t >> 13;
        const float4* p = (const float4*)(x + (size_t)row * KDIM + w * 32);
        uint32_t word = 0;
#pragma unroll
        for (int q = 0; q < 8; q++) {
            float4 v = p[q];
            word |= (v.x >= 0.5f ? 1u : 0u) << (q * 4 + 0);
            word |= (v.y >= 0.5f ? 1u : 0u) << (q * 4 + 1);
            word |= (v.z >= 0.5f ? 1u : 0u) << (q * 4 + 2);
            word |= (v.w >= 0.5f ? 1u : 0u) << (q * 4 + 3);
        }
        g_Ap[(size_t)w * BDIM + row] = word;
    } else {
        int i = (b - 4096) * 256 + tid;
        if (i < KDIM) { g_colsum[0][i] = 0; g_colsum[1][i] = 0; g_colsum[2][i] = 0; }
        if (i < N2) { g_sumsq[i] = 0ull; g_expsum[i] = 0.f; g_cmax[i] = -2147483647 - 1; }
    }
}

// chunky wtrans: W[K,Nw] f32 -> g_Bp[w][n]; block covers 128 k-rows x 32 n-cols.
__global__ void k_wtrans(const float* __restrict__ W, int Nw) {
    __shared__ float tbuf[128][33];
    int gx = Nw / 32;
    int n0 = (blockIdx.x % gx) * 32;
    int k0 = (blockIdx.x / gx) * 128;
    int tx = threadIdx.x & 31, ty = threadIdx.x >> 5;   // 32 x 8
#pragma unroll
    for (int q = 0; q < 16; q++)
        tbuf[ty + 8 * q][tx] = W[(size_t)(k0 + ty + 8 * q) * Nw + n0 + tx];
    __syncthreads();
    // 8 warps x 16 (g,n) pairs: p = warp*16 + i; g = p>>5 (k-word), n = p&31
#pragma unroll
    for (int i = 0; i < 16; i++) {
        int p = ty * 16 + i;
        int g = p >> 5, n = p & 31;
        uint32_t b = __ballot_sync(0xffffffffu, tbuf[g * 32 + tx][n] >= 0.f);
        if (tx == 0) g_Bp[(size_t)(k0 / 32 + g) * Nw + n0 + n] = b;
    }
}

// binarize hidden activation: bit = (8192*s >= colsum) exactly (gamma>0, beta=0)
__global__ void k_binact(int N, const float* __restrict__ gamma, int layer) {
    int t = blockIdx.x * 256 + threadIdx.x;       // (BDIM * N/32) threads
    int row = t & (BDIM - 1), w = t >> 13;
    float g = gamma[layer];
    const uint4* sp = (const uint4*)(g_S16 + (size_t)row * N + w * 32);
    const int4* cp = (const int4*)(&g_colsum[layer][w * 32]);
    uint32_t word = 0;
#pragma unroll
    for (int q = 0; q < 4; q++) {
        uint4 u = sp[q];
        int4 c0 = cp[2 * q], c1 = cp[2 * q + 1];
        int s0 = (short)(u.x & 0xFFFF), s1 = (short)(u.x >> 16);
        int s2 = (short)(u.y & 0xFFFF), s3 = (short)(u.y >> 16);
        int s4 = (short)(u.z & 0xFFFF), s5 = (short)(u.z >> 16);
        int s6 = (short)(u.w & 0xFFFF), s7 = (short)(u.w >> 16);
        word |= (s0 * 8192 >= c0.x ? 1u : 0u) << (q * 8 + 0);
        word |= (s1 * 8192 >= c0.y ? 1u : 0u) << (q * 8 + 1);
        word |= (s2 * 8192 >= c0.z ? 1u : 0u) << (q * 8 + 2);
        word |= (s3 * 8192 >= c0.w ? 1u : 0u) << (q * 8 + 3);
        word |= (s4 * 8192 >= c1.x ? 1u : 0u) << (q * 8 + 4);
        word |= (s5 * 8192 >= c1.y ? 1u : 0u) << (q * 8 + 5);
        word |= (s6 * 8192 >= c1.z ? 1u : 0u) << (q * 8 + 6);
        word |= (s7 * 8192 >= c1.w ? 1u : 0u) << (q * 8 + 7);
    }
    if (g <= 0.f) word = 0xFFFFFFFFu;   // a == beta == 0 -> +1
    g_Ap[(size_t)w * BDIM + row] = word;
}

// per-column BN params derived identically in both softmax passes
__device__ __forceinline__ void bn_params(int col, const float* gamma,
                                          float& g, float& mu, float& am) {
    double sum = (double)g_colsum[2][col];
    double dmu = sum * (1.0 / 8192.0);
    double var = (double)g_sumsq[col] * (1.0 / 8192.0) - dmu * dmu;
    g = (float)((double)gamma[2] / sqrt(var + 1e-5));
    mu = (float)dmu;
    am = ((float)g_cmax[col] - mu) * g;   // beta cancels in softmax
}

// pass 1: expsum only (no exp store)
__global__ void k_soft1(const float* __restrict__ gamma) {
    const int N = N2;
    int col = blockIdx.x * 256 + threadIdx.x;
    size_t r0 = (size_t)blockIdx.y * 64;
    float g, mu, am;
    bn_params(col, gamma, g, mu, am);
    const short* p = g_S16 + r0 * N + col;
    float acc = 0.f;
    for (int r = 0; r < 64; r++)
        acc += expf(((float)p[(size_t)r * N] - mu) * g - am);
    atomicAdd(&g_expsum[col], acc);
}

// pass 2: recompute exp (bit-identical expf), normalize, write out
__global__ void k_soft2(float* __restrict__ out, const float* __restrict__ gamma) {
    const int N = N2;
    int col = blockIdx.x * 256 + threadIdx.x;
    size_t r0 = (size_t)blockIdx.y * 64;
    float g, mu, am;
    bn_params(col, gamma, g, mu, am);
    float inv = 1.0f / g_expsum[col];
    const short* p = g_S16 + r0 * N + col;
    float* o = out + r0 * N + col;
    for (int r = 0; r < 64; r++) {
        float e = expf(((float)p[(size_t)r * N] - mu) * g - am);
        o[(size_t)r * N] = e * inv;
    }
}

// ---------------- launch ----------------
extern "C" void kernel_launch(void* const* d_in, const int* in_sizes, int n_in,
                              void* d_out, int out_size) {
    const float* x     = (const float*)d_in[0];
    const float* W0    = (const float*)d_in[1];
    const float* W1    = (const float*)d_in[2];
    const float* W2    = (const float*)d_in[3];
    const float* gamma = (const float*)d_in[4];
    float* out = (float*)d_out;

    cudaFuncSetAttribute(k_gemm, cudaFuncAttributeMaxDynamicSharedMemorySize, GEMM_SMEM);

    k_pre<<<4112, 256>>>(x);                      // binx + zero
    k_wtrans<<<4096, 256>>>(W0, 4096);
    k_gemm<<<dim3(64, 128), 256, GEMM_SMEM>>>(4096, 0, 0, 1, 2, 4);
    k_binact<<<4096, 256>>>(4096, gamma, 0);
    k_wtrans<<<4096, 256>>>(W1, 4096);
    k_gemm<<<dim3(64, 128), 256, GEMM_SMEM>>>(4096, 1, 0, 1, 2, 4);
    k_binact<<<4096, 256>>>(4096, gamma, 1);
    k_wtrans<<<1024, 256>>>(W2, 1024);
    k_gemm<<<dim3(16, 128), 256, GEMM_SMEM>>>(1024, 2, 1, 1, 2, 4);
    k_soft1<<<dim3(4, 128), 256>>>(gamma);
    k_soft2<<<dim3(4, 128), 256>>>(out, gamma);
}

// round 16
// speedup vs baseline: 1.0180x; 1.0147x over previous
#include <cuda_runtime.h>
#include <cstdint>

// ---------------- problem dims (fixed) ----------------
#define BDIM 8192
#define KDIM 4096
#define N2   1024
#define KW   (KDIM / 32)   // 128 k-words

// ---------------- device scratch (no mallocs allowed) ----------------
__device__ uint32_t g_Ap[(size_t)KW * BDIM];        // packed activations [w][row]
__device__ uint32_t g_Bp[3][(size_t)KW * KDIM];     // packed weights per layer [w][n]
__device__ short    g_S16[(size_t)BDIM * KDIM];
__device__ int                g_colsum[3][KDIM];    // per-layer colsum
__device__ unsigned long long g_sumsq[N2];
__device__ int                g_cmax[N2];
__device__ float              g_expsum[N2];

// ---------------- helpers ----------------
__device__ __forceinline__ uint32_t smem_u32(const void* p) {
    uint32_t a;
    asm("{ .reg .u64 t; cvta.to.shared.u64 t, %1; cvt.u32.u64 %0, t; }" : "=r"(a) : "l"(p));
    return a;
}
__device__ __forceinline__ void cp16(uint32_t s, const void* g) {
    asm volatile("cp.async.cg.shared.global [%0], [%1], 16;" :: "r"(s), "l"(g));
}
#define CP_COMMIT() asm volatile("cp.async.commit_group;" ::: "memory")
#define CP_WAITN(n) asm volatile("cp.async.wait_group %0;" :: "n"(n) : "memory")

__device__ __forceinline__ void ld4(uint32_t* d, const uint32_t* p) {
    uint4 t = *(const uint4*)p; d[0] = t.x; d[1] = t.y; d[2] = t.z; d[3] = t.w;
}
// full adder on bit-planes: s = a^b^c (LOP3 0x96), carry = maj(a,b,c) (LOP3 0xE8)
__device__ __forceinline__ void fa(uint32_t a, uint32_t b, uint32_t c,
                                   uint32_t& s, uint32_t& cy) {
    asm("lop3.b32 %0, %2, %3, %4, 0x96;\n\t"
        "lop3.b32 %1, %2, %3, %4, 0xE8;"
        : "=r"(s), "=r"(cy) : "r"(a), "r"(b), "r"(c));
}

// ---------------- XNOR-popc GEMM with CSA compression (frozen from R12) ----------
// CTA tile 64x64, 256 thr, thread tile 4x4. Two 64-kw stages (32KB each,
// dynamic smem 64KB, 2 CTAs/SM) -> only 2 barriers per tile.
#define STG_W 8192     // words per stage (A 4096 + B 4096)
#define GEMM_SMEM (STG_W * 4 * 2)

__global__ void __launch_bounds__(256, 2) k_gemm(int N, int layer, int doStats,
                                                 int one, int two, int four) {
    extern __shared__ __align__(16) uint32_t smem[];
    const uint32_t sb = smem_u32(smem);
    const int tid = threadIdx.x;
    // bijective remap: tx = {b2b1b0, b7}, ty = {b6..b3}
    const int tx = (tid & 7) | ((tid >> 4) & 8);
    const int ty = (tid >> 3) & 15;
    const size_t m0 = (size_t)blockIdx.y * 64;
    const size_t n0 = (size_t)blockIdx.x * 64;

    const uint32_t* Ab = g_Ap + m0;            // + w*BDIM + m
    const uint32_t* Bb = g_Bp[layer] + n0;     // + w*N + n

    auto load_chunk = [&](int c, int st) {
        uint32_t base = sb + st * (STG_W * 4);
#pragma unroll
        for (int i = 0; i < 4; i++) {
            int idx = tid + i * 256;                 // 0..1023 : 64 kw x 16 segs
            int kw = idx >> 4, seg = idx & 15;
            cp16(base + kw * 256 + seg * 16,
                 Ab + (size_t)(c * 64 + kw) * BDIM + seg * 4);
            cp16(base + 16384 + kw * 256 + seg * 16,
                 Bb + (size_t)(c * 64 + kw) * N + seg * 4);
        }
    };

    int acc[4][4];
#pragma unroll
    for (int i = 0; i < 4; i++)
#pragma unroll
        for (int j = 0; j < 4; j++) acc[i][j] = 0;

    load_chunk(0, 0); CP_COMMIT();
    load_chunk(1, 1); CP_COMMIT();

    auto compute_chunk = [&](const uint32_t* stp) {
#pragma unroll
        for (int g = 0; g < 8; g++) {
            const uint32_t* gp = stp + g * 512;      // 8-kw group
            uint32_t a[8][4], b[8][4];
#pragma unroll
            for (int w = 0; w < 8; w++) {
                ld4(a[w], gp + w * 64 + ty * 4);
                ld4(b[w], gp + 4096 + w * 64 + tx * 4);
            }
#pragma unroll
            for (int i = 0; i < 4; i++)
#pragma unroll
                for (int j = 0; j < 4; j++) {
                    uint32_t x0 = a[0][i] ^ b[0][j], x1 = a[1][i] ^ b[1][j];
                    uint32_t x2 = a[2][i] ^ b[2][j], x3 = a[3][i] ^ b[3][j];
                    uint32_t x4 = a[4][i] ^ b[4][j], x5 = a[5][i] ^ b[5][j];
                    uint32_t x6 = a[6][i] ^ b[6][j], x7 = a[7][i] ^ b[7][j];
                    uint32_t s1, c1, s2, c2, s3, c3, s5, c5;
                    fa(x0, x1, x2, s1, c1);     // -> s1(w1), c1(w2)
                    fa(x3, x4, x5, s2, c2);     // -> s2(w1), c2(w2)
                    fa(s1, s2, x6, s3, c3);     // -> s3(w1), c3(w2)
                    fa(c1, c2, c3, s5, c5);     // -> s5(w2), c5(w4)
                    // remaining planes: s3(w1), x7(w1), s5(w2), c5(w4)
                    int p0 = __popc(s3), p1 = __popc(x7);
                    int p2 = __popc(s5), p3 = __popc(c5);
                    // weighted accumulate on fma pipe; weights are kernel args
                    // so ptxas cannot strength-reduce mad -> add
                    asm("mad.lo.s32 %0, %1, %5, %0;\n\t"
                        "mad.lo.s32 %0, %2, %5, %0;\n\t"
                        "mad.lo.s32 %0, %3, %6, %0;\n\t"
                        "mad.lo.s32 %0, %4, %7, %0;"
                        : "+r"(acc[i][j])
                        : "r"(p0), "r"(p1), "r"(p2), "r"(p3),
                          "r"(one), "r"(two), "r"(four));
                }
        }
    };

    CP_WAITN(1);
    __syncthreads();
    compute_chunk(smem);
    CP_WAITN(0);
    __syncthreads();
    compute_chunk(smem + STG_W);
    __syncthreads();   // k-loop smem dead; reuse for reductions below

    // ---- epilogue 1: s = 4096 - 2*P, exact int16 stores ----
#pragma unroll
    for (int i = 0; i < 4; i++) {
        size_t row = m0 + ty * 4 + i;
        int s0 = 4096 - 2 * acc[i][0], s1 = 4096 - 2 * acc[i][1];
        int s2 = 4096 - 2 * acc[i][2], s3 = 4096 - 2 * acc[i][3];
        uint32_t lo = (uint16_t)s0 | ((uint32_t)(uint16_t)s1 << 16);
        uint32_t hi = (uint16_t)s2 | ((uint32_t)(uint16_t)s3 << 16);
        *(uint2*)&g_S16[row * N + n0 + tx * 4] = make_uint2(lo, hi);
    }

    // ---- epilogue 2: fused per-column reductions ----
    int* colbuf = (int*)smem;
    unsigned* sqbuf = (unsigned*)smem + 64;
    int* mxbuf = (int*)smem + 128;
    if (tid < 64) {
        colbuf[tid] = 0;
        if (doStats) { sqbuf[tid] = 0u; mxbuf[tid] = -2147483647 - 1; }
    }
    __syncthreads();
#pragma unroll
    for (int j = 0; j < 4; j++) {
        int cl = tx * 4 + j;
        int cs = 4 * 4096 - 2 * (acc[0][j] + acc[1][j] + acc[2][j] + acc[3][j]);
        atomicAdd(&colbuf[cl], cs);
        if (doStats) {
            int sq = 0, mx = -2147483647 - 1;
#pragma unroll
            for (int i = 0; i < 4; i++) {
                int s = 4096 - 2 * acc[i][j];
                sq += s * s; mx = max(mx, s);
            }
            atomicAdd(&sqbuf[cl], (unsigned)sq);
            atomicMax(&mxbuf[cl], mx);
        }
    }
    __syncthreads();
    if (tid < 64) {
        atomicAdd(&g_colsum[layer][n0 + tid], colbuf[tid]);
        if (doStats) {
            atomicAdd(&g_sumsq[n0 + tid], (unsigned long long)sqbuf[tid]);
            atomicMax(&g_cmax[n0 + tid], mxbuf[tid]);
        }
    }
}

// ---------------- aux kernels ----------------

// k_pre: blocks [0,4096) binarize x; blocks [4096,4112) zero accumulators.
__global__ void k_pre(const float* __restrict__ x) {
    int b = blockIdx.x, tid = threadIdx.x;
    if (b < 4096) {
        int t = b * 256 + tid;
        int row = t & (BDIM - 1), w = t >> 13;
        const float4* p = (const float4*)(x + (size_t)row * KDIM + w * 32);
        uint32_t word = 0;
#pragma unroll
        for (int q = 0; q < 8; q++) {
            float4 v = p[q];
            word |= (v.x >= 0.5f ? 1u : 0u) << (q * 4 + 0);
            word |= (v.y >= 0.5f ? 1u : 0u) << (q * 4 + 1);
            word |= (v.z >= 0.5f ? 1u : 0u) << (q * 4 + 2);
            word |= (v.w >= 0.5f ? 1u : 0u) << (q * 4 + 3);
        }
        g_Ap[(size_t)w * BDIM + row] = word;
    } else {
        int i = (b - 4096) * 256 + tid;
        if (i < KDIM) { g_colsum[0][i] = 0; g_colsum[1][i] = 0; g_colsum[2][i] = 0; }
        if (i < N2) { g_sumsq[i] = 0ull; g_expsum[i] = 0.f; g_cmax[i] = -2147483647 - 1; }
    }
}

// chunky wtrans: W[K,Nw] f32 -> g_Bp[layer][w][n]; block covers 128 k x 32 n.
__global__ void k_wtrans(const float* __restrict__ W, int Nw, int layer) {
    __shared__ float tbuf[128][33];
    int gx = Nw / 32;
    int n0 = (blockIdx.x % gx) * 32;
    int k0 = (blockIdx.x / gx) * 128;
    int tx = threadIdx.x & 31, ty = threadIdx.x >> 5;   // 32 x 8
#pragma unroll
    for (int q = 0; q < 16; q++)
        tbuf[ty + 8 * q][tx] = W[(size_t)(k0 + ty + 8 * q) * Nw + n0 + tx];
    __syncthreads();
    // 8 warps x 16 (g,n) pairs: p = warp*16 + i; g = p>>5 (k-word), n = p&31
#pragma unroll
    for (int i = 0; i < 16; i++) {
        int p = ty * 16 + i;
        int g = p >> 5, n = p & 31;
        uint32_t b = __ballot_sync(0xffffffffu, tbuf[g * 32 + tx][n] >= 0.f);
        if (tx == 0) g_Bp[layer][(size_t)(k0 / 32 + g) * Nw + n0 + n] = b;
    }
}

// binarize hidden activation: bit = (8192*s >= colsum) exactly (gamma>0, beta=0)
__global__ void k_binact(int N, const float* __restrict__ gamma, int layer) {
    int t = blockIdx.x * 256 + threadIdx.x;       // (BDIM * N/32) threads
    int row = t & (BDIM - 1), w = t >> 13;
    float g = gamma[layer];
    const uint4* sp = (const uint4*)(g_S16 + (size_t)row * N + w * 32);
    const int4* cp = (const int4*)(&g_colsum[layer][w * 32]);
    uint32_t word = 0;
#pragma unroll
    for (int q = 0; q < 4; q++) {
        uint4 u = sp[q];
        int4 c0 = cp[2 * q], c1 = cp[2 * q + 1];
        int s0 = (short)(u.x & 0xFFFF), s1 = (short)(u.x >> 16);
        int s2 = (short)(u.y & 0xFFFF), s3 = (short)(u.y >> 16);
        int s4 = (short)(u.z & 0xFFFF), s5 = (short)(u.z >> 16);
        int s6 = (short)(u.w & 0xFFFF), s7 = (short)(u.w >> 16);
        word |= (s0 * 8192 >= c0.x ? 1u : 0u) << (q * 8 + 0);
        word |= (s1 * 8192 >= c0.y ? 1u : 0u) << (q * 8 + 1);
        word |= (s2 * 8192 >= c0.z ? 1u : 0u) << (q * 8 + 2);
        word |= (s3 * 8192 >= c0.w ? 1u : 0u) << (q * 8 + 3);
        word |= (s4 * 8192 >= c1.x ? 1u : 0u) << (q * 8 + 4);
        word |= (s5 * 8192 >= c1.y ? 1u : 0u) << (q * 8 + 5);
        word |= (s6 * 8192 >= c1.z ? 1u : 0u) << (q * 8 + 6);
        word |= (s7 * 8192 >= c1.w ? 1u : 0u) << (q * 8 + 7);
    }
    if (g <= 0.f) word = 0xFFFFFFFFu;   // a == beta == 0 -> +1
    g_Ap[(size_t)w * BDIM + row] = word;
}

// per-column BN params derived identically in both softmax passes
__device__ __forceinline__ void bn_params(int col, const float* gamma,
                                          float& g, float& mu, float& am) {
    double sum = (double)g_colsum[2][col];
    double dmu = sum * (1.0 / 8192.0);
    double var = (double)g_sumsq[col] * (1.0 / 8192.0) - dmu * dmu;
    g = (float)((double)gamma[2] / sqrt(var + 1e-5));
    mu = (float)dmu;
    am = ((float)g_cmax[col] - mu) * g;   // beta cancels in softmax
}

// pass 1: expsum only (no exp store)
__global__ void k_soft1(const float* __restrict__ gamma) {
    const int N = N2;
    int col = blockIdx.x * 256 + threadIdx.x;
    size_t r0 = (size_t)blockIdx.y * 64;
    float g, mu, am;
    bn_params(col, gamma, g, mu, am);
    const short* p = g_S16 + r0 * N + col;
    float acc = 0.f;
    for (int r = 0; r < 64; r++)
        acc += expf(((float)p[(size_t)r * N] - mu) * g - am);
    atomicAdd(&g_expsum[col], acc);
}

// pass 2: recompute exp (bit-identical expf), normalize, write out
__global__ void k_soft2(float* __restrict__ out, const float* __restrict__ gamma) {
    const int N = N2;
    int col = blockIdx.x * 256 + threadIdx.x;
    size_t r0 = (size_t)blockIdx.y * 64;
    float g, mu, am;
    bn_params(col, gamma, g, mu, am);
    float inv = 1.0f / g_expsum[col];
    const short* p = g_S16 + r0 * N + col;
    float* o = out + r0 * N + col;
    for (int r = 0; r < 64; r++) {
        float e = expf(((float)p[(size_t)r * N] - mu) * g - am);
        o[(size_t)r * N] = e * inv;
    }
}

// ---------------- launch (fork/join wtrans onto a side stream; per-layer
// weight buffers eliminate all WAR hazards between streams) ----------------
extern "C" void kernel_launch(void* const* d_in, const int* in_sizes, int n_in,
                              void* d_out, int out_size) {
    const float* x     = (const float*)d_in[0];
    const float* W0    = (const float*)d_in[1];
    const float* W1    = (const float*)d_in[2];
    const float* W2    = (const float*)d_in[3];
    const float* gamma = (const float*)d_in[4];
    float* out = (float*)d_out;

    cudaFuncSetAttribute(k_gemm, cudaFuncAttributeMaxDynamicSharedMemorySize, GEMM_SMEM);

    cudaStream_t s1;
    cudaStreamCreateWithFlags(&s1, cudaStreamNonBlocking);
    cudaEvent_t eFork, e0, e1, e2;
    cudaEventCreateWithFlags(&eFork, cudaEventDisableTiming);
    cudaEventCreateWithFlags(&e0, cudaEventDisableTiming);
    cudaEventCreateWithFlags(&e1, cudaEventDisableTiming);
    cudaEventCreateWithFlags(&e2, cudaEventDisableTiming);

    // fork side stream from the (possibly capturing) main stream
    cudaEventRecord(eFork, 0);
    cudaStreamWaitEvent(s1, eFork, 0);

    // side stream: three weight transposes, each into its OWN buffer
    k_wtrans<<<4096, 256, 0, s1>>>(W0, 4096, 0);
    cudaEventRecord(e0, s1);
    k_wtrans<<<4096, 256, 0, s1>>>(W1, 4096, 1);
    cudaEventRecord(e1, s1);
    k_wtrans<<<1024, 256, 0, s1>>>(W2, 1024, 2);
    cudaEventRecord(e2, s1);

    // main stream
    k_pre<<<4112, 256>>>(x);                      // binx + zero (overlaps wtrans0)
    cudaStreamWaitEvent(0, e0, 0);
    k_gemm<<<dim3(64, 128), 256, GEMM_SMEM>>>(4096, 0, 0, 1, 2, 4);  // || wtrans1/2
    k_binact<<<4096, 256>>>(4096, gamma, 0);
    cudaStreamWaitEvent(0, e1, 0);
    k_gemm<<<dim3(64, 128), 256, GEMM_SMEM>>>(4096, 1, 0, 1, 2, 4);  // || wtrans2
    k_binact<<<4096, 256>>>(4096, gamma, 1);
    cudaStreamWaitEvent(0, e2, 0);                // join: side stream fully merged
    k_gemm<<<dim3(16, 128), 256, GEMM_SMEM>>>(1024, 2, 1, 1, 2, 4);
    k_soft1<<<dim3(4, 128), 256>>>(gamma);
    k_soft2<<<dim3(4, 128), 256>>>(out, gamma);

    cudaEventDestroy(eFork);
    cudaEventDestroy(e0);
    cudaEventDestroy(e1);
    cudaEventDestroy(e2);
    cudaStreamDestroy(s1);
}